// round 7
// baseline (speedup 1.0000x reference)
#include <cuda_runtime.h>
#include <cuda_fp16.h>
#include <cstdint>
#include <cstddef>

// ============================================================================
// SpanMarkerV1 on sm_100 (legacy tensor path): fp16 mma.sync m16n8k16, fp32 acc.
//   B=8, L=512, D=768, S=6144, H=3072
// 128x256x64 block tiles, 64x64 warp tiles (8 warps), cp.async double buffer,
// ldmatrix.x4 fragment loads, conflict-free stride-72-half smem, 1 CTA/SM.
// ============================================================================

#define BM 128
#define BN 256
#define BK 64
#define LSTR 72                         // halves; 144B row stride, conflict-free
#define A_H (BM * LSTR)                 // 9216 halves
#define B_H (BN * LSTR)                 // 18432 halves
#define STAGE_ALL (A_H + B_H)           // halves per stage
#define GSMEM_BYTES (2 * STAGE_ALL * 2) // 110592 bytes

// -------- scratch (device globals; allocations are forbidden) ---------------
__device__ __half g_hidden[150994944ULL]; // 49152*3072 fp16 (302 MB), reused
__device__ __half g_srep[3145728ULL];     // 4096*768
__device__ __half g_erep[3145728ULL];     // 4096*768
__device__ __half g_cat[75497472ULL];     // 49152*1536 (151 MB)
__device__ __half g_hh[3145728ULL];       // h in fp16
__device__ __half g_sw1t[2359296ULL];     // [3072,768]  = W^T [N,K]
__device__ __half g_ew1t[2359296ULL];
__device__ __half g_ow1t[4718592ULL];     // [3072,1536]
__device__ __half g_sw2t[2359296ULL];     // [768,3072]
__device__ __half g_ew2t[2359296ULL];
__device__ __half g_ow2t[2359296ULL];

__device__ __forceinline__ void cp16(uint32_t smem_addr, const void* gmem_ptr) {
    asm volatile("cp.async.cg.shared.global [%0], [%1], 16;\n" :: "r"(smem_addr), "l"(gmem_ptr));
}

__device__ __forceinline__ void ldsm4(uint32_t* r, uint32_t addr) {
    asm volatile("ldmatrix.sync.aligned.m8n8.x4.shared.b16 {%0,%1,%2,%3}, [%4];"
                 : "=r"(r[0]), "=r"(r[1]), "=r"(r[2]), "=r"(r[3]) : "r"(addr));
}

__device__ __forceinline__ void mma_f16(float c[4], const uint32_t a[4], const uint32_t b[2]) {
    asm volatile(
        "mma.sync.aligned.m16n8k16.row.col.f32.f16.f16.f32 "
        "{%0,%1,%2,%3}, {%4,%5,%6,%7}, {%8,%9}, {%0,%1,%2,%3};\n"
        : "+f"(c[0]), "+f"(c[1]), "+f"(c[2]), "+f"(c[3])
        : "r"(a[0]), "r"(a[1]), "r"(a[2]), "r"(a[3]),
          "r"(b[0]), "r"(b[1]));
}

// ============================================================================
// C[M,N] = act(A[M,K] @ W + bias);  A fp16 [M,K], Bt = W^T fp16 [N,K].
// c_half: store fp16 (intermediates) else fp32 (final output).
// ============================================================================
__global__ __launch_bounds__(256, 1)
void gemm_f16(const __half* __restrict__ A, const __half* __restrict__ Bt,
              const float* __restrict__ bias, void* __restrict__ Cv,
              int M, int N, int K, int relu, int c_half)
{
    extern __shared__ __half sm[];
    const uint32_t sbase = (uint32_t)__cvta_generic_to_shared(sm);

    const int tid  = threadIdx.x;
    const int warp = tid >> 5;
    const int lane = tid & 31;
    const int wm = warp & 1;    // 2 x 64-row warp tiles
    const int wn = warp >> 1;   // 4 x 64-col warp tiles
    const int tileM = blockIdx.y * BM;
    const int tileN = blockIdx.x * BN;

    float acc[4][8][4];
#pragma unroll
    for (int mi = 0; mi < 4; mi++)
#pragma unroll
        for (int ni = 0; ni < 8; ni++)
#pragma unroll
            for (int j = 0; j < 4; j++) acc[mi][ni][j] = 0.0f;

    // ---- staging: A 128x64 halves = 1024 chunks, B 256x64 = 2048 chunks ----
    auto stage = [&](int s, int k0) {
        const uint32_t abase = sbase + s * (STAGE_ALL * 2);
        const uint32_t bbase = abase + A_H * 2;
#pragma unroll
        for (int i = 0; i < 4; i++) {
            int ch  = tid + i * 256;
            int row = ch >> 3;
            int co  = (ch & 7) << 3;
            cp16(abase + (row * LSTR + co) * 2, A + (size_t)(tileM + row) * K + k0 + co);
        }
#pragma unroll
        for (int i = 0; i < 8; i++) {
            int ch  = tid + i * 256;
            int row = ch >> 3;
            int co  = (ch & 7) << 3;
            cp16(bbase + (row * LSTR + co) * 2, Bt + (size_t)(tileN + row) * K + k0 + co);
        }
        asm volatile("cp.async.commit_group;\n" ::);
    };

    // ldmatrix per-lane source coords
    const int arow = lane & 15;            // A: lanes 0-15 rows, 16-31 -> +8 cols
    const int acol = (lane >> 4) << 3;
    const int bg   = lane >> 3;            // B: 4 groups of 8
    const int brow = ((bg >> 1) << 3) + (lane & 7);
    const int bcol = (bg & 1) << 3;

    const int KT = K / BK;
    stage(0, 0);

    for (int kt = 0; kt < KT; kt++) {
        if (kt + 1 < KT) {
            stage((kt + 1) & 1, (kt + 1) * BK);
            asm volatile("cp.async.wait_group 1;\n" ::);
        } else {
            asm volatile("cp.async.wait_group 0;\n" ::);
        }
        __syncthreads();

        const uint32_t abase = sbase + (kt & 1) * (STAGE_ALL * 2);
        const uint32_t bbase = abase + A_H * 2;

#pragma unroll
        for (int kk = 0; kk < 4; kk++) {           // four k16 steps
            const int kb = kk << 4;
            uint32_t af[4][4], bf[8][2];
#pragma unroll
            for (int mi = 0; mi < 4; mi++) {
                int m0 = wm * 64 + mi * 16;
                ldsm4(af[mi], abase + ((m0 + arow) * LSTR + kb + acol) * 2);
            }
#pragma unroll
            for (int p = 0; p < 4; p++) {          // 2 n-octets per ldmatrix.x4
                int n0 = wn * 64 + p * 16;
                uint32_t r[4];
                ldsm4(r, bbase + ((n0 + brow) * LSTR + kb + bcol) * 2);
                bf[2 * p][0] = r[0]; bf[2 * p][1] = r[1];
                bf[2 * p + 1][0] = r[2]; bf[2 * p + 1][1] = r[3];
            }
#pragma unroll
            for (int mi = 0; mi < 4; mi++)
#pragma unroll
                for (int ni = 0; ni < 8; ni++)
                    mma_f16(acc[mi][ni], af[mi], bf[ni]);
        }
        __syncthreads();
    }

    // ---- epilogue: bias + optional relu; fp16 or fp32 store ----
#pragma unroll
    for (int mi = 0; mi < 4; mi++) {
#pragma unroll
        for (int ni = 0; ni < 8; ni++) {
            int m = tileM + wm * 64 + mi * 16 + (lane >> 2);
            int n = tileN + wn * 64 + ni * 8 + ((lane & 3) << 1);
            float b0 = bias[n], b1 = bias[n + 1];
            float v0 = acc[mi][ni][0] + b0;
            float v1 = acc[mi][ni][1] + b1;
            float v2 = acc[mi][ni][2] + b0;
            float v3 = acc[mi][ni][3] + b1;
            if (relu) {
                v0 = fmaxf(v0, 0.0f); v1 = fmaxf(v1, 0.0f);
                v2 = fmaxf(v2, 0.0f); v3 = fmaxf(v3, 0.0f);
            }
            if (c_half) {
                __half* C = (__half*)Cv;
                *(__half2*)&C[(size_t)m * N + n]       = __floats2half2_rn(v0, v1);
                *(__half2*)&C[(size_t)(m + 8) * N + n] = __floats2half2_rn(v2, v3);
            } else {
                float* C = (float*)Cv;
                *(float2*)&C[(size_t)m * N + n]       = make_float2(v0, v1);
                *(float2*)&C[(size_t)(m + 8) * N + n] = make_float2(v2, v3);
            }
        }
    }
}

// ---- weight transpose + fp32->fp16: out[C,R] = half(in[R,C]^T) --------------
__global__ void transpose_h(const float* __restrict__ in, __half* __restrict__ out,
                            int R, int C)
{
    __shared__ float t[32][33];
    const int tx = threadIdx.x, ty = threadIdx.y;   // 32 x 8
    const int x0 = blockIdx.x * 32, y0 = blockIdx.y * 32;
#pragma unroll
    for (int i = 0; i < 32; i += 8)
        t[ty + i][tx] = in[(size_t)(y0 + ty + i) * C + x0 + tx];
    __syncthreads();
#pragma unroll
    for (int i = 0; i < 32; i += 8)
        out[(size_t)(x0 + ty + i) * R + y0 + tx] = __float2half_rn(t[tx][ty + i]);
}

// ---- elementwise fp32->fp16 -------------------------------------------------
__global__ void f2h_kernel(const float* __restrict__ in, __half* __restrict__ out, int n)
{
    int i = blockIdx.x * 256 + threadIdx.x;
    if (i < n) out[i] = __float2half_rn(in[i]);
}

// ---- gather spans + concat + relu (fp16) ------------------------------------
__global__ void gather_cat_kernel(const __half* __restrict__ srep, const __half* __restrict__ erep,
                                  const int* __restrict__ span, __half* __restrict__ cat)
{
    const int r  = blockIdx.x;     // 0..49151 (b*6144 + s)
    const int c8 = threadIdx.x;    // 0..191, 8 halves (16B) each
    const int b  = r / 6144;

    uint4 u;
    if (c8 < 96) {
        int i0 = span[((size_t)r << 1) + 0];
        u = *(const uint4*)&srep[((size_t)(b * 512 + i0)) * 768 + (c8 << 3)];
    } else {
        int i1 = span[((size_t)r << 1) + 1];
        u = *(const uint4*)&erep[((size_t)(b * 512 + i1)) * 768 + ((c8 - 96) << 3)];
    }
    const __half2 z = __floats2half2_rn(0.0f, 0.0f);
    __half2* p = (__half2*)&u;
#pragma unroll
    for (int j = 0; j < 4; j++) p[j] = __hmax2(p[j], z);
    *(uint4*)&cat[(size_t)r * 1536 + (c8 << 3)] = u;
}

extern "C" void kernel_launch(void* const* d_in, const int* in_sizes, int n_in,
                              void* d_out, int out_size)
{
    const float* h    = (const float*)d_in[0];
    const int*   span = (const int*)  d_in[1];
    const float* sw1  = (const float*)d_in[2];
    const float* sb1  = (const float*)d_in[3];
    const float* sw2  = (const float*)d_in[4];
    const float* sb2  = (const float*)d_in[5];
    const float* ew1  = (const float*)d_in[6];
    const float* eb1  = (const float*)d_in[7];
    const float* ew2  = (const float*)d_in[8];
    const float* eb2  = (const float*)d_in[9];
    const float* ow1  = (const float*)d_in[10];
    const float* ob1  = (const float*)d_in[11];
    const float* ow2  = (const float*)d_in[12];
    const float* ob2  = (const float*)d_in[13];
    float* out = (float*)d_out;

    __half *hidden, *srep, *erep, *cat, *hh;
    __half *sw1t, *ew1t, *ow1t, *sw2t, *ew2t, *ow2t;
    cudaGetSymbolAddress((void**)&hidden, g_hidden);
    cudaGetSymbolAddress((void**)&srep,   g_srep);
    cudaGetSymbolAddress((void**)&erep,   g_erep);
    cudaGetSymbolAddress((void**)&cat,    g_cat);
    cudaGetSymbolAddress((void**)&hh,     g_hh);
    cudaGetSymbolAddress((void**)&sw1t,   g_sw1t);
    cudaGetSymbolAddress((void**)&ew1t,   g_ew1t);
    cudaGetSymbolAddress((void**)&ow1t,   g_ow1t);
    cudaGetSymbolAddress((void**)&sw2t,   g_sw2t);
    cudaGetSymbolAddress((void**)&ew2t,   g_ew2t);
    cudaGetSymbolAddress((void**)&ow2t,   g_ow2t);

    cudaFuncSetAttribute(gemm_f16, cudaFuncAttributeMaxDynamicSharedMemorySize, GSMEM_BYTES);

    const dim3 tb(32, 8);
    // weight transposes (+fp16 convert), and h convert
    transpose_h<<<dim3(3072 / 32,  768 / 32), tb>>>(sw1, sw1t,  768, 3072);
    transpose_h<<<dim3(3072 / 32,  768 / 32), tb>>>(ew1, ew1t,  768, 3072);
    transpose_h<<<dim3(3072 / 32, 1536 / 32), tb>>>(ow1, ow1t, 1536, 3072);
    transpose_h<<<dim3( 768 / 32, 3072 / 32), tb>>>(sw2, sw2t, 3072,  768);
    transpose_h<<<dim3( 768 / 32, 3072 / 32), tb>>>(ew2, ew2t, 3072,  768);
    transpose_h<<<dim3( 768 / 32, 3072 / 32), tb>>>(ow2, ow2t, 3072,  768);
    f2h_kernel<<<(3145728 + 255) / 256, 256>>>(h, hh, 3145728);

    const dim3 blk(256);
    // start projection
    gemm_f16<<<dim3(12, 32), blk, GSMEM_BYTES>>>(hh,     sw1t, sb1, hidden, 4096, 3072,  768, 1, 1);
    gemm_f16<<<dim3( 3, 32), blk, GSMEM_BYTES>>>(hidden, sw2t, sb2, srep,   4096,  768, 3072, 0, 1);
    // end projection
    gemm_f16<<<dim3(12, 32), blk, GSMEM_BYTES>>>(hh,     ew1t, eb1, hidden, 4096, 3072,  768, 1, 1);
    gemm_f16<<<dim3( 3, 32), blk, GSMEM_BYTES>>>(hidden, ew2t, eb2, erep,   4096,  768, 3072, 0, 1);
    // span gather + concat + relu
    gather_cat_kernel<<<49152, 192>>>(srep, erep, span, cat);
    // output projection
    gemm_f16<<<dim3(12, 384), blk, GSMEM_BYTES>>>(cat,    ow1t, ob1, hidden, 49152, 3072, 1536, 1, 1);
    gemm_f16<<<dim3( 3, 384), blk, GSMEM_BYTES>>>(hidden, ow2t, ob2, out,    49152,  768, 3072, 0, 0);
}

// round 8
// speedup vs baseline: 1.1874x; 1.1874x over previous
#include <cuda_runtime.h>
#include <cuda_fp16.h>
#include <cstdint>
#include <cstddef>

// ============================================================================
// SpanMarkerV1 on sm_100 (legacy tensor path): fp16 mma.sync m16n8k16, fp32 acc.
//   B=8, L=512, D=768, S=6144, H=3072
// 128x128x64 tiles, 32x64 warp tiles, 3-stage cp.async ring with a single
// __syncthreads per ktile, ldmatrix.x4, stride-72-half smem, 2 CTAs/SM.
// ============================================================================

#define BM 128
#define BN 128
#define BK 64
#define LSTR 72                         // halves; 144B row stride, conflict-free
#define STAGE_H (BM * LSTR)             // 9216 halves per operand tile
#define STAGE_ALL (2 * STAGE_H)         // A + B per stage (halves)
#define NSTAGE 3
#define GSMEM_BYTES (NSTAGE * STAGE_ALL * 2)  // 110592 bytes

// -------- scratch (device globals; allocations are forbidden) ---------------
__device__ __half g_hidden[150994944ULL]; // 49152*3072 fp16 (302 MB), reused
__device__ __half g_srep[3145728ULL];     // 4096*768
__device__ __half g_erep[3145728ULL];     // 4096*768
__device__ __half g_cat[75497472ULL];     // 49152*1536 (151 MB)
__device__ __half g_hh[3145728ULL];       // h in fp16
__device__ __half g_sw1t[2359296ULL];     // [3072,768]  = W^T [N,K]
__device__ __half g_ew1t[2359296ULL];
__device__ __half g_ow1t[4718592ULL];     // [3072,1536]
__device__ __half g_sw2t[2359296ULL];     // [768,3072]
__device__ __half g_ew2t[2359296ULL];
__device__ __half g_ow2t[2359296ULL];

__device__ __forceinline__ void cp16(uint32_t smem_addr, const void* gmem_ptr) {
    asm volatile("cp.async.cg.shared.global [%0], [%1], 16;\n" :: "r"(smem_addr), "l"(gmem_ptr));
}

__device__ __forceinline__ void ldsm4(uint32_t* r, uint32_t addr) {
    asm volatile("ldmatrix.sync.aligned.m8n8.x4.shared.b16 {%0,%1,%2,%3}, [%4];"
                 : "=r"(r[0]), "=r"(r[1]), "=r"(r[2]), "=r"(r[3]) : "r"(addr));
}

__device__ __forceinline__ void mma_f16(float c[4], const uint32_t a[4], const uint32_t b[2]) {
    asm volatile(
        "mma.sync.aligned.m16n8k16.row.col.f32.f16.f16.f32 "
        "{%0,%1,%2,%3}, {%4,%5,%6,%7}, {%8,%9}, {%0,%1,%2,%3};\n"
        : "+f"(c[0]), "+f"(c[1]), "+f"(c[2]), "+f"(c[3])
        : "r"(a[0]), "r"(a[1]), "r"(a[2]), "r"(a[3]),
          "r"(b[0]), "r"(b[1]));
}

// ============================================================================
// C[M,N] = act(A[M,K] @ W + bias);  A fp16 [M,K], Bt = W^T fp16 [N,K].
// c_half: store fp16 (intermediates) else fp32 (final output).
// ============================================================================
__global__ __launch_bounds__(256, 2)
void gemm_f16(const __half* __restrict__ A, const __half* __restrict__ Bt,
              const float* __restrict__ bias, void* __restrict__ Cv,
              int M, int N, int K, int relu, int c_half)
{
    extern __shared__ __half sm[];
    const uint32_t sbase = (uint32_t)__cvta_generic_to_shared(sm);

    const int tid  = threadIdx.x;
    const int warp = tid >> 5;
    const int lane = tid & 31;
    const int wm = warp & 3;    // 32-row warp tile
    const int wn = warp >> 2;   // 64-col warp tile
    const int tileM = blockIdx.y * BM;
    const int tileN = blockIdx.x * BN;

    float acc[2][8][4];
#pragma unroll
    for (int mi = 0; mi < 2; mi++)
#pragma unroll
        for (int ni = 0; ni < 8; ni++)
#pragma unroll
            for (int j = 0; j < 4; j++) acc[mi][ni][j] = 0.0f;

    // ---- staging: per ktile, A and B each 128x64 halves = 1024 16B chunks --
    auto stage = [&](int s, int k0) {
        const uint32_t abase = sbase + s * (STAGE_ALL * 2);
        const uint32_t bbase = abase + STAGE_H * 2;
#pragma unroll
        for (int i = 0; i < 4; i++) {
            int ch  = tid + i * 256;
            int row = ch >> 3;
            int co  = (ch & 7) << 3;        // halves
            cp16(abase + (row * LSTR + co) * 2, A  + (size_t)(tileM + row) * K + k0 + co);
            cp16(bbase + (row * LSTR + co) * 2, Bt + (size_t)(tileN + row) * K + k0 + co);
        }
        asm volatile("cp.async.commit_group;\n" ::);
    };

    // ldmatrix per-lane source coords
    const int arow = lane & 15;            // A: lanes 0-15 -> rows, 16-31 -> +8 cols
    const int acol = (lane >> 4) << 3;
    const int bg   = lane >> 3;            // B: 4 groups of 8
    const int brow = ((bg >> 1) << 3) + (lane & 7);
    const int bcol = (bg & 1) << 3;

    const int KT = K / BK;                 // >= 12 for all our shapes
    stage(0, 0);
    stage(1, BK);

    int cons = 0, ss = 2;
    for (int kt = 0; kt < KT; kt++) {
        if (kt + 1 < KT) asm volatile("cp.async.wait_group 1;\n" ::);
        else             asm volatile("cp.async.wait_group 0;\n" ::);
        __syncthreads();   // single barrier per ktile (3-stage ring makes the
                           // end-of-iteration stage target a buffer all warps
                           // finished before this barrier)

        const uint32_t abase = sbase + cons * (STAGE_ALL * 2);
        const uint32_t bbase = abase + STAGE_H * 2;

#pragma unroll
        for (int kk = 0; kk < 4; kk++) {           // four k16 steps
            const int kb = kk << 4;
            uint32_t af[2][4], bf[8][2];
#pragma unroll
            for (int mi = 0; mi < 2; mi++) {
                int m0 = wm * 32 + mi * 16;
                ldsm4(af[mi], abase + ((m0 + arow) * LSTR + kb + acol) * 2);
            }
#pragma unroll
            for (int p = 0; p < 4; p++) {          // 2 n-octets per ldmatrix.x4
                int n0 = wn * 64 + p * 16;
                uint32_t r[4];
                ldsm4(r, bbase + ((n0 + brow) * LSTR + kb + bcol) * 2);
                bf[2 * p][0] = r[0]; bf[2 * p][1] = r[1];
                bf[2 * p + 1][0] = r[2]; bf[2 * p + 1][1] = r[3];
            }
#pragma unroll
            for (int mi = 0; mi < 2; mi++)
#pragma unroll
                for (int ni = 0; ni < 8; ni++)
                    mma_f16(acc[mi][ni], af[mi], bf[ni]);
        }

        if (kt + 2 < KT) stage(ss, (kt + 2) * BK);
        if (++cons == NSTAGE) cons = 0;
        if (++ss == NSTAGE) ss = 0;
    }

    // ---- epilogue: bias + optional relu; fp16 or fp32 store ----
#pragma unroll
    for (int mi = 0; mi < 2; mi++) {
#pragma unroll
        for (int ni = 0; ni < 8; ni++) {
            int m = tileM + wm * 32 + mi * 16 + (lane >> 2);
            int n = tileN + wn * 64 + ni * 8 + ((lane & 3) << 1);
            float b0 = bias[n], b1 = bias[n + 1];
            float v0 = acc[mi][ni][0] + b0;
            float v1 = acc[mi][ni][1] + b1;
            float v2 = acc[mi][ni][2] + b0;
            float v3 = acc[mi][ni][3] + b1;
            if (relu) {
                v0 = fmaxf(v0, 0.0f); v1 = fmaxf(v1, 0.0f);
                v2 = fmaxf(v2, 0.0f); v3 = fmaxf(v3, 0.0f);
            }
            if (c_half) {
                __half* C = (__half*)Cv;
                *(__half2*)&C[(size_t)m * N + n]       = __floats2half2_rn(v0, v1);
                *(__half2*)&C[(size_t)(m + 8) * N + n] = __floats2half2_rn(v2, v3);
            } else {
                float* C = (float*)Cv;
                *(float2*)&C[(size_t)m * N + n]       = make_float2(v0, v1);
                *(float2*)&C[(size_t)(m + 8) * N + n] = make_float2(v2, v3);
            }
        }
    }
}

// ---- fused weight prep: all 6 transposes (+fp16) in ONE launch --------------
// z selects the weight; each z transposes in[R,C] -> out[C,R] (fp16).
struct WDesc { const float* in; __half* out; int R, C; };
__global__ void transpose_all(const float* sw1, const float* ew1, const float* ow1,
                              const float* sw2, const float* ew2, const float* ow2,
                              __half* sw1t, __half* ew1t, __half* ow1t,
                              __half* sw2t, __half* ew2t, __half* ow2t)
{
    const float* in; __half* out; int R, C;
    switch (blockIdx.z) {
        case 0: in = sw1; out = sw1t; R =  768; C = 3072; break;
        case 1: in = ew1; out = ew1t; R =  768; C = 3072; break;
        case 2: in = ow1; out = ow1t; R = 1536; C = 3072; break;
        case 3: in = sw2; out = sw2t; R = 3072; C =  768; break;
        case 4: in = ew2; out = ew2t; R = 3072; C =  768; break;
        default:in = ow2; out = ow2t; R = 3072; C =  768; break;
    }
    const int x0 = blockIdx.x * 32, y0 = blockIdx.y * 32;
    if (x0 >= C || y0 >= R) return;

    __shared__ float t[32][33];
    const int tx = threadIdx.x, ty = threadIdx.y;   // 32 x 8
#pragma unroll
    for (int i = 0; i < 32; i += 8)
        t[ty + i][tx] = in[(size_t)(y0 + ty + i) * C + x0 + tx];
    __syncthreads();
#pragma unroll
    for (int i = 0; i < 32; i += 8)
        out[(size_t)(x0 + ty + i) * R + y0 + tx] = __float2half_rn(t[tx][ty + i]);
}

// ---- elementwise fp32->fp16 -------------------------------------------------
__global__ void f2h_kernel(const float* __restrict__ in, __half* __restrict__ out, int n)
{
    int i = blockIdx.x * 256 + threadIdx.x;
    if (i < n) out[i] = __float2half_rn(in[i]);
}

// ---- gather spans + concat + relu (fp16) ------------------------------------
__global__ void gather_cat_kernel(const __half* __restrict__ srep, const __half* __restrict__ erep,
                                  const int* __restrict__ span, __half* __restrict__ cat)
{
    const int r  = blockIdx.x;     // 0..49151 (b*6144 + s)
    const int c8 = threadIdx.x;    // 0..191, 8 halves (16B) each
    const int b  = r / 6144;

    uint4 u;
    if (c8 < 96) {
        int i0 = span[((size_t)r << 1) + 0];
        u = *(const uint4*)&srep[((size_t)(b * 512 + i0)) * 768 + (c8 << 3)];
    } else {
        int i1 = span[((size_t)r << 1) + 1];
        u = *(const uint4*)&erep[((size_t)(b * 512 + i1)) * 768 + ((c8 - 96) << 3)];
    }
    const __half2 z = __floats2half2_rn(0.0f, 0.0f);
    __half2* p = (__half2*)&u;
#pragma unroll
    for (int j = 0; j < 4; j++) p[j] = __hmax2(p[j], z);
    *(uint4*)&cat[(size_t)r * 1536 + (c8 << 3)] = u;
}

extern "C" void kernel_launch(void* const* d_in, const int* in_sizes, int n_in,
                              void* d_out, int out_size)
{
    const float* h    = (const float*)d_in[0];
    const int*   span = (const int*)  d_in[1];
    const float* sw1  = (const float*)d_in[2];
    const float* sb1  = (const float*)d_in[3];
    const float* sw2  = (const float*)d_in[4];
    const float* sb2  = (const float*)d_in[5];
    const float* ew1  = (const float*)d_in[6];
    const float* eb1  = (const float*)d_in[7];
    const float* ew2  = (const float*)d_in[8];
    const float* eb2  = (const float*)d_in[9];
    const float* ow1  = (const float*)d_in[10];
    const float* ob1  = (const float*)d_in[11];
    const float* ow2  = (const float*)d_in[12];
    const float* ob2  = (const float*)d_in[13];
    float* out = (float*)d_out;

    __half *hidden, *srep, *erep, *cat, *hh;
    __half *sw1t, *ew1t, *ow1t, *sw2t, *ew2t, *ow2t;
    cudaGetSymbolAddress((void**)&hidden, g_hidden);
    cudaGetSymbolAddress((void**)&srep,   g_srep);
    cudaGetSymbolAddress((void**)&erep,   g_erep);
    cudaGetSymbolAddress((void**)&cat,    g_cat);
    cudaGetSymbolAddress((void**)&hh,     g_hh);
    cudaGetSymbolAddress((void**)&sw1t,   g_sw1t);
    cudaGetSymbolAddress((void**)&ew1t,   g_ew1t);
    cudaGetSymbolAddress((void**)&ow1t,   g_ow1t);
    cudaGetSymbolAddress((void**)&sw2t,   g_sw2t);
    cudaGetSymbolAddress((void**)&ew2t,   g_ew2t);
    cudaGetSymbolAddress((void**)&ow2t,   g_ow2t);

    cudaFuncSetAttribute(gemm_f16, cudaFuncAttributeMaxDynamicSharedMemorySize, GSMEM_BYTES);

    // launch 1: all weight transposes; launch 2: h convert
    transpose_all<<<dim3(96, 96, 6), dim3(32, 8)>>>(sw1, ew1, ow1, sw2, ew2, ow2,
                                                    sw1t, ew1t, ow1t, sw2t, ew2t, ow2t);
    f2h_kernel<<<(3145728 + 255) / 256, 256>>>(h, hh, 3145728);

    const dim3 blk(256);
    // launches 3-6: projection GEMMs (launch 6 = ncu capture slot)
    gemm_f16<<<dim3(24, 32), blk, GSMEM_BYTES>>>(hh,     sw1t, sb1, hidden, 4096, 3072,  768, 1, 1);
    gemm_f16<<<dim3( 6, 32), blk, GSMEM_BYTES>>>(hidden, sw2t, sb2, srep,   4096,  768, 3072, 0, 1);
    gemm_f16<<<dim3(24, 32), blk, GSMEM_BYTES>>>(hh,     ew1t, eb1, hidden, 4096, 3072,  768, 1, 1);
    gemm_f16<<<dim3( 6, 32), blk, GSMEM_BYTES>>>(hidden, ew2t, eb2, erep,   4096,  768, 3072, 0, 1);
    // span gather + concat + relu
    gather_cat_kernel<<<49152, 192>>>(srep, erep, span, cat);
    // output projection
    gemm_f16<<<dim3(24, 384), blk, GSMEM_BYTES>>>(cat,    ow1t, ob1, hidden, 49152, 3072, 1536, 1, 1);
    gemm_f16<<<dim3( 6, 384), blk, GSMEM_BYTES>>>(hidden, ow2t, ob2, out,    49152,  768, 3072, 0, 0);
}

// round 9
// speedup vs baseline: 1.2257x; 1.0322x over previous
#include <cuda_runtime.h>
#include <cuda_fp16.h>
#include <cstdint>
#include <cstddef>

// ============================================================================
// SpanMarkerV1 on sm_100: fp16 mma.sync m16n8k16, fp32 accum.
//   B=8, L=512, D=768, S=6144, H=3072
// 128x128x64 tiles, 32x64 warp tiles, 3-stage cp.async ring (1 barrier/ktile),
// ldmatrix.x4, stride-72-half smem, 2 CTAs/SM.
// Structural fusions: layer-1 pair -> one GEMM (weight concat); layer-2 pair
// -> one z-batched GEMM (relu in epilogue); span-gather folded into the big
// GEMM's A staging (cat buffer eliminated).
// ============================================================================

#define BM 128
#define BN 128
#define BK 64
#define LSTR 72                         // halves; 144B row stride, conflict-free
#define STAGE_H (BM * LSTR)             // 9216 halves per operand tile
#define STAGE_ALL (2 * STAGE_H)         // A + B per stage (halves)
#define NSTAGE 3
#define GSMEM_BYTES (NSTAGE * STAGE_ALL * 2)  // 110592 bytes

// -------- scratch (device globals; allocations are forbidden) ---------------
__device__ __half g_hidden[150994944ULL]; // 49152*3072 fp16 (302 MB), reused
__device__ __half g_serelu[6291456ULL];   // [2][4096*768] relu'd span reps
__device__ __half g_hh[3145728ULL];       // h in fp16
__device__ __half g_w1cat[4718592ULL];    // [6144,768]  = [sw1t; ew1t]
__device__ __half g_w2cat[4718592ULL];    // [1536,3072] = [sw2t; ew2t]
__device__ __half g_ow1t[4718592ULL];     // [3072,1536]
__device__ __half g_ow2t[2359296ULL];     // [768,3072]
__device__ float  g_b1cat[6144];
__device__ float  g_b2cat[1536];

__device__ __forceinline__ void cp16(uint32_t smem_addr, const void* gmem_ptr) {
    asm volatile("cp.async.cg.shared.global [%0], [%1], 16;\n" :: "r"(smem_addr), "l"(gmem_ptr));
}

__device__ __forceinline__ void ldsm4(uint32_t* r, uint32_t addr) {
    asm volatile("ldmatrix.sync.aligned.m8n8.x4.shared.b16 {%0,%1,%2,%3}, [%4];"
                 : "=r"(r[0]), "=r"(r[1]), "=r"(r[2]), "=r"(r[3]) : "r"(addr));
}

__device__ __forceinline__ void mma_f16(float c[4], const uint32_t a[4], const uint32_t b[2]) {
    asm volatile(
        "mma.sync.aligned.m16n8k16.row.col.f32.f16.f16.f32 "
        "{%0,%1,%2,%3}, {%4,%5,%6,%7}, {%8,%9}, {%0,%1,%2,%3};\n"
        : "+f"(c[0]), "+f"(c[1]), "+f"(c[2]), "+f"(c[3])
        : "r"(a[0]), "r"(a[1]), "r"(a[2]), "r"(a[3]),
          "r"(b[0]), "r"(b[1]));
}

// ============================================================================
// Shared GEMM mainloop+epilogue. A fp16 [M,? stride lda], Bt fp16 [N,K] K-major.
// ============================================================================
__device__ __forceinline__ void gemm_core(
    const __half* __restrict__ A, int lda, const __half* __restrict__ Bt,
    const float* __restrict__ bias, void* __restrict__ Cv, int ldc,
    int N, int K, int relu, int c_half, int tileM, int tileN, uint32_t sbase)
{
    const int tid  = threadIdx.x;
    const int warp = tid >> 5;
    const int lane = tid & 31;
    const int wm = warp & 3;
    const int wn = warp >> 2;

    float acc[2][8][4];
#pragma unroll
    for (int mi = 0; mi < 2; mi++)
#pragma unroll
        for (int ni = 0; ni < 8; ni++)
#pragma unroll
            for (int j = 0; j < 4; j++) acc[mi][ni][j] = 0.0f;

    auto stage = [&](int s, int k0) {
        const uint32_t abase = sbase + s * (STAGE_ALL * 2);
        const uint32_t bbase = abase + STAGE_H * 2;
#pragma unroll
        for (int i = 0; i < 4; i++) {
            int ch  = tid + i * 256;
            int row = ch >> 3;
            int co  = (ch & 7) << 3;
            cp16(abase + (row * LSTR + co) * 2, A  + (size_t)(tileM + row) * lda + k0 + co);
            cp16(bbase + (row * LSTR + co) * 2, Bt + (size_t)(tileN + row) * K   + k0 + co);
        }
        asm volatile("cp.async.commit_group;\n" ::);
    };

    const int arow = lane & 15;
    const int acol = (lane >> 4) << 3;
    const int bg   = lane >> 3;
    const int brow = ((bg >> 1) << 3) + (lane & 7);
    const int bcol = (bg & 1) << 3;

    const int KT = K / BK;
    stage(0, 0);
    stage(1, BK);

    int cons = 0, ss = 2;
    for (int kt = 0; kt < KT; kt++) {
        if (kt + 1 < KT) asm volatile("cp.async.wait_group 1;\n" ::);
        else             asm volatile("cp.async.wait_group 0;\n" ::);
        __syncthreads();

        const uint32_t abase = sbase + cons * (STAGE_ALL * 2);
        const uint32_t bbase = abase + STAGE_H * 2;

#pragma unroll
        for (int kk = 0; kk < 4; kk++) {
            const int kb = kk << 4;
            uint32_t af[2][4], bf[8][2];
#pragma unroll
            for (int mi = 0; mi < 2; mi++) {
                int m0 = wm * 32 + mi * 16;
                ldsm4(af[mi], abase + ((m0 + arow) * LSTR + kb + acol) * 2);
            }
#pragma unroll
            for (int p = 0; p < 4; p++) {
                int n0 = wn * 64 + p * 16;
                uint32_t r[4];
                ldsm4(r, bbase + ((n0 + brow) * LSTR + kb + bcol) * 2);
                bf[2 * p][0] = r[0]; bf[2 * p][1] = r[1];
                bf[2 * p + 1][0] = r[2]; bf[2 * p + 1][1] = r[3];
            }
#pragma unroll
            for (int mi = 0; mi < 2; mi++)
#pragma unroll
                for (int ni = 0; ni < 8; ni++)
                    mma_f16(acc[mi][ni], af[mi], bf[ni]);
        }

        if (kt + 2 < KT) stage(ss, (kt + 2) * BK);
        if (++cons == NSTAGE) cons = 0;
        if (++ss == NSTAGE) ss = 0;
    }

#pragma unroll
    for (int mi = 0; mi < 2; mi++) {
#pragma unroll
        for (int ni = 0; ni < 8; ni++) {
            int m = tileM + wm * 32 + mi * 16 + (lane >> 2);
            int n = tileN + wn * 64 + ni * 8 + ((lane & 3) << 1);
            float b0 = bias[n - tileN + (tileN)], b1 = bias[n + 1];
            b0 = bias[n];
            float v0 = acc[mi][ni][0] + b0;
            float v1 = acc[mi][ni][1] + b1;
            float v2 = acc[mi][ni][2] + b0;
            float v3 = acc[mi][ni][3] + b1;
            if (relu) {
                v0 = fmaxf(v0, 0.0f); v1 = fmaxf(v1, 0.0f);
                v2 = fmaxf(v2, 0.0f); v3 = fmaxf(v3, 0.0f);
            }
            if (c_half) {
                __half* C = (__half*)Cv;
                *(__half2*)&C[(size_t)m * ldc + n]       = __floats2half2_rn(v0, v1);
                *(__half2*)&C[(size_t)(m + 8) * ldc + n] = __floats2half2_rn(v2, v3);
            } else {
                float* C = (float*)Cv;
                *(float2*)&C[(size_t)m * ldc + n]       = make_float2(v0, v1);
                *(float2*)&C[(size_t)(m + 8) * ldc + n] = make_float2(v2, v3);
            }
        }
    }
}

// ---- general GEMM wrapper ---------------------------------------------------
__global__ __launch_bounds__(256, 2)
void gemm_k(const __half* __restrict__ A, int lda, const __half* __restrict__ Bt,
            const float* __restrict__ bias, void* __restrict__ Cv, int ldc,
            int N, int K, int relu, int c_half)
{
    extern __shared__ __half sm[];
    gemm_core(A, lda, Bt, bias, Cv, ldc, N, K, relu, c_half,
              blockIdx.y * BM, blockIdx.x * BN,
              (uint32_t)__cvta_generic_to_shared(sm));
}

// ---- layer-2 pair, z-batched: serelu[z] = relu(hidden_se[:, z*3072:] @ w2cat[z]) ----
__global__ __launch_bounds__(256, 2)
void gemm_l2(const __half* __restrict__ hidden, const __half* __restrict__ w2cat,
             const float* __restrict__ b2cat, __half* __restrict__ serelu)
{
    extern __shared__ __half sm[];
    const int z = blockIdx.z;
    gemm_core(hidden + z * 3072, 6144,
              w2cat + (size_t)z * 768 * 3072,
              b2cat + z * 768,
              serelu + (size_t)z * 4096 * 768, 768,
              768, 3072, 1, 1,
              blockIdx.y * BM, blockIdx.x * BN,
              (uint32_t)__cvta_generic_to_shared(sm));
}

// ============================================================================
// Big GEMM with fused span-gather A staging:
//   A row r (of 49152) = [serelu_s[b, i0(r)] , serelu_e[b, i1(r)]]  (K=1536)
// ============================================================================
__global__ __launch_bounds__(256, 2)
void gemm_gather(const __half* __restrict__ serelu, const int* __restrict__ span,
                 const __half* __restrict__ Bt, const float* __restrict__ bias,
                 __half* __restrict__ C)
{
    extern __shared__ __half sm[];
    const uint32_t sbase = (uint32_t)__cvta_generic_to_shared(sm);
    __shared__ int sidx[2 * BM];

    const int tid  = threadIdx.x;
    const int warp = tid >> 5;
    const int lane = tid & 31;
    const int wm = warp & 3;
    const int wn = warp >> 2;
    const int tileM = blockIdx.y * BM;
    const int tileN = blockIdx.x * BN;
    const int bb = tileM / 6144;                  // batch (6144 % 128 == 0)
    const __half* __restrict__ srelu = serelu;
    const __half* __restrict__ erelu = serelu + 4096 * 768;

    if (tid < BM) {
        sidx[2 * tid]     = span[2 * (size_t)(tileM + tid)];
        sidx[2 * tid + 1] = span[2 * (size_t)(tileM + tid) + 1];
    }
    __syncthreads();

    float acc[2][8][4];
#pragma unroll
    for (int mi = 0; mi < 2; mi++)
#pragma unroll
        for (int ni = 0; ni < 8; ni++)
#pragma unroll
            for (int j = 0; j < 4; j++) acc[mi][ni][j] = 0.0f;

    const int N = 3072, K = 1536;

    auto stage = [&](int s, int k0) {
        const uint32_t abase = sbase + s * (STAGE_ALL * 2);
        const uint32_t bbase = abase + STAGE_H * 2;
        const bool first = (k0 < 768);
        const __half* __restrict__ rep = first ? srelu : erelu;
        const int kc = first ? k0 : (k0 - 768);
        const int ip = first ? 0 : 1;
#pragma unroll
        for (int i = 0; i < 4; i++) {
            int ch  = tid + i * 256;
            int row = ch >> 3;
            int co  = (ch & 7) << 3;
            const __half* src = rep + (size_t)(bb * 512 + sidx[2 * row + ip]) * 768 + kc + co;
            cp16(abase + (row * LSTR + co) * 2, src);
            cp16(bbase + (row * LSTR + co) * 2, Bt + (size_t)(tileN + row) * K + k0 + co);
        }
        asm volatile("cp.async.commit_group;\n" ::);
    };

    const int arow = lane & 15;
    const int acol = (lane >> 4) << 3;
    const int bg   = lane >> 3;
    const int brow = ((bg >> 1) << 3) + (lane & 7);
    const int bcol = (bg & 1) << 3;

    const int KT = K / BK;   // 24
    stage(0, 0);
    stage(1, BK);

    int cons = 0, ss = 2;
    for (int kt = 0; kt < KT; kt++) {
        if (kt + 1 < KT) asm volatile("cp.async.wait_group 1;\n" ::);
        else             asm volatile("cp.async.wait_group 0;\n" ::);
        __syncthreads();

        const uint32_t abase = sbase + cons * (STAGE_ALL * 2);
        const uint32_t bbase = abase + STAGE_H * 2;

#pragma unroll
        for (int kk = 0; kk < 4; kk++) {
            const int kb = kk << 4;
            uint32_t af[2][4], bf[8][2];
#pragma unroll
            for (int mi = 0; mi < 2; mi++) {
                int m0 = wm * 32 + mi * 16;
                ldsm4(af[mi], abase + ((m0 + arow) * LSTR + kb + acol) * 2);
            }
#pragma unroll
            for (int p = 0; p < 4; p++) {
                int n0 = wn * 64 + p * 16;
                uint32_t r[4];
                ldsm4(r, bbase + ((n0 + brow) * LSTR + kb + bcol) * 2);
                bf[2 * p][0] = r[0]; bf[2 * p][1] = r[1];
                bf[2 * p + 1][0] = r[2]; bf[2 * p + 1][1] = r[3];
            }
#pragma unroll
            for (int mi = 0; mi < 2; mi++)
#pragma unroll
                for (int ni = 0; ni < 8; ni++)
                    mma_f16(acc[mi][ni], af[mi], bf[ni]);
        }

        if (kt + 2 < KT) stage(ss, (kt + 2) * BK);
        if (++cons == NSTAGE) cons = 0;
        if (++ss == NSTAGE) ss = 0;
    }

#pragma unroll
    for (int mi = 0; mi < 2; mi++) {
#pragma unroll
        for (int ni = 0; ni < 8; ni++) {
            int m = tileM + wm * 32 + mi * 16 + (lane >> 2);
            int n = tileN + wn * 64 + ni * 8 + ((lane & 3) << 1);
            float b0 = bias[n], b1 = bias[n + 1];
            float v0 = fmaxf(acc[mi][ni][0] + b0, 0.0f);
            float v1 = fmaxf(acc[mi][ni][1] + b1, 0.0f);
            float v2 = fmaxf(acc[mi][ni][2] + b0, 0.0f);
            float v3 = fmaxf(acc[mi][ni][3] + b1, 0.0f);
            *(__half2*)&C[(size_t)m * N + n]       = __floats2half2_rn(v0, v1);
            *(__half2*)&C[(size_t)(m + 8) * N + n] = __floats2half2_rn(v2, v3);
        }
    }
}

// ---- fused weight prep: all 6 transposes (+fp16) in ONE launch --------------
__global__ void transpose_all(const float* sw1, const float* ew1, const float* ow1,
                              const float* sw2, const float* ew2, const float* ow2,
                              __half* w1cat, __half* w2cat, __half* ow1t, __half* ow2t)
{
    const float* in; __half* out; int R, C;
    switch (blockIdx.z) {
        case 0: in = sw1; out = w1cat;                          R =  768; C = 3072; break;
        case 1: in = ew1; out = w1cat + (size_t)3072 * 768;     R =  768; C = 3072; break;
        case 2: in = ow1; out = ow1t;                           R = 1536; C = 3072; break;
        case 3: in = sw2; out = w2cat;                          R = 3072; C =  768; break;
        case 4: in = ew2; out = w2cat + (size_t)768 * 3072;     R = 3072; C =  768; break;
        default:in = ow2; out = ow2t;                           R = 3072; C =  768; break;
    }
    const int x0 = blockIdx.x * 32, y0 = blockIdx.y * 32;
    if (x0 >= C || y0 >= R) return;

    __shared__ float t[32][33];
    const int tx = threadIdx.x, ty = threadIdx.y;   // 32 x 8
#pragma unroll
    for (int i = 0; i < 32; i += 8)
        t[ty + i][tx] = in[(size_t)(y0 + ty + i) * C + x0 + tx];
    __syncthreads();
#pragma unroll
    for (int i = 0; i < 32; i += 8)
        out[(size_t)(x0 + ty + i) * R + y0 + tx] = __float2half_rn(t[tx][ty + i]);
}

// ---- bias concats + h convert ----------------------------------------------
__global__ void bias_cat(const float* sb1, const float* eb1, const float* sb2, const float* eb2,
                         float* b1cat, float* b2cat)
{
    int i = blockIdx.x * 256 + threadIdx.x;
    if (i < 3072) { b1cat[i] = sb1[i]; b1cat[3072 + i] = eb1[i]; }
    if (i < 768)  { b2cat[i] = sb2[i]; b2cat[768 + i]  = eb2[i]; }
}

__global__ void f2h_kernel(const float* __restrict__ in, __half* __restrict__ out, int n)
{
    int i = blockIdx.x * 256 + threadIdx.x;
    if (i < n) out[i] = __float2half_rn(in[i]);
}

extern "C" void kernel_launch(void* const* d_in, const int* in_sizes, int n_in,
                              void* d_out, int out_size)
{
    const float* h    = (const float*)d_in[0];
    const int*   span = (const int*)  d_in[1];
    const float* sw1  = (const float*)d_in[2];
    const float* sb1  = (const float*)d_in[3];
    const float* sw2  = (const float*)d_in[4];
    const float* sb2  = (const float*)d_in[5];
    const float* ew1  = (const float*)d_in[6];
    const float* eb1  = (const float*)d_in[7];
    const float* ew2  = (const float*)d_in[8];
    const float* eb2  = (const float*)d_in[9];
    const float* ow1  = (const float*)d_in[10];
    const float* ob1  = (const float*)d_in[11];
    const float* ow2  = (const float*)d_in[12];
    const float* ob2  = (const float*)d_in[13];
    float* out = (float*)d_out;

    __half *hidden, *serelu, *hh, *w1cat, *w2cat, *ow1t, *ow2t;
    float *b1cat, *b2cat;
    cudaGetSymbolAddress((void**)&hidden, g_hidden);
    cudaGetSymbolAddress((void**)&serelu, g_serelu);
    cudaGetSymbolAddress((void**)&hh,     g_hh);
    cudaGetSymbolAddress((void**)&w1cat,  g_w1cat);
    cudaGetSymbolAddress((void**)&w2cat,  g_w2cat);
    cudaGetSymbolAddress((void**)&ow1t,   g_ow1t);
    cudaGetSymbolAddress((void**)&ow2t,   g_ow2t);
    cudaGetSymbolAddress((void**)&b1cat,  g_b1cat);
    cudaGetSymbolAddress((void**)&b2cat,  g_b2cat);

    cudaFuncSetAttribute(gemm_k,      cudaFuncAttributeMaxDynamicSharedMemorySize, GSMEM_BYTES);
    cudaFuncSetAttribute(gemm_l2,     cudaFuncAttributeMaxDynamicSharedMemorySize, GSMEM_BYTES);
    cudaFuncSetAttribute(gemm_gather, cudaFuncAttributeMaxDynamicSharedMemorySize, GSMEM_BYTES);

    // 1: all weight transposes   2: bias concats   3: h -> fp16
    transpose_all<<<dim3(96, 96, 6), dim3(32, 8)>>>(sw1, ew1, ow1, sw2, ew2, ow2,
                                                    w1cat, w2cat, ow1t, ow2t);
    bias_cat<<<12, 256>>>(sb1, eb1, sb2, eb2, b1cat, b2cat);
    f2h_kernel<<<(3145728 + 255) / 256, 256>>>(h, hh, 3145728);

    const dim3 blk(256);
    // 4: fused layer-1  hidden_se[4096,6144] = relu(hh @ w1cat + b1cat)
    gemm_k<<<dim3(48, 32), blk, GSMEM_BYTES>>>(hh, 768, w1cat, b1cat, hidden, 6144,
                                               6144, 768, 1, 1);
    // 5: batched layer-2  serelu[z] = relu(hidden_se[:, z] @ w2cat[z] + b2cat[z])
    gemm_l2<<<dim3(6, 32, 2), blk, GSMEM_BYTES>>>(hidden, w2cat, b2cat, serelu);
    // 6: big GEMM with fused gather  hidden[49152,3072] = relu(gather_cat @ ow1t + ob1)
    gemm_gather<<<dim3(24, 384), blk, GSMEM_BYTES>>>(serelu, span, ow1t, ob1, hidden);
    // 7: final  out[49152,768] = hidden @ ow2t + ob2
    gemm_k<<<dim3(6, 384), blk, GSMEM_BYTES>>>(hidden, 3072, ow2t, ob2, out, 768,
                                               768, 3072, 0, 0);
}

// round 10
// speedup vs baseline: 2.2971x; 1.8741x over previous
#include <cuda_runtime.h>
#include <cuda_fp16.h>
#include <cstdint>
#include <cstddef>

// ============================================================================
// SpanMarkerV1 on sm_100: fp16 mma.sync m16n8k16, fp32 accum.
//   B=8, L=512, D=768, S=6144, H=3072
// Key algebraic fusion this round: the 464-GF gather-GEMM is replaced by
//   U = serelu_s @ ow1_top, V = serelu_e @ ow1_bot   (38.6 GF, fp32 out)
//   hidden[r] = relu(U[b,i0(r)] + V[b,i1(r)] + ob1)  (bandwidth pass)
// since gathered rows repeat (~12x reuse) and cat@ow1 splits by halves.
// GEMM core: 128x128x64 tiles, 32x64 warp tiles, 3-stage cp.async ring,
// ldmatrix.x4, stride-72-half smem, 2 CTAs/SM.
// ============================================================================

#define BM 128
#define BN 128
#define BK 64
#define LSTR 72                         // halves; 144B row stride, conflict-free
#define STAGE_H (BM * LSTR)             // 9216 halves per operand tile
#define STAGE_ALL (2 * STAGE_H)         // A + B per stage (halves)
#define NSTAGE 3
#define GSMEM_BYTES (NSTAGE * STAGE_ALL * 2)  // 110592 bytes

// -------- scratch (device globals; allocations are forbidden) ---------------
__device__ __half g_hidden[150994944ULL]; // reused: [4096,6144] then [49152,3072]
__device__ __half g_serelu[6291456ULL];   // [2][4096,768] relu'd reps
__device__ __half g_hh[3145728ULL];       // h in fp16
__device__ __half g_w1cat[4718592ULL];    // [6144,768]  = [sw1t; ew1t]
__device__ __half g_w2cat[4718592ULL];    // [1536,3072] = [sw2t; ew2t]
__device__ __half g_ow1t[4718592ULL];     // [3072,1536]
__device__ __half g_ow2t[2359296ULL];     // [768,3072]
__device__ float  g_uv[25165824ULL];      // [2][4096,3072] fp32 U,V (96 MB)
__device__ float  g_b1cat[6144];
__device__ float  g_b2cat[1536];
__device__ float  g_zbias[3072];          // zero-initialized

__device__ __forceinline__ void cp16(uint32_t smem_addr, const void* gmem_ptr) {
    asm volatile("cp.async.cg.shared.global [%0], [%1], 16;\n" :: "r"(smem_addr), "l"(gmem_ptr));
}

__device__ __forceinline__ void ldsm4(uint32_t* r, uint32_t addr) {
    asm volatile("ldmatrix.sync.aligned.m8n8.x4.shared.b16 {%0,%1,%2,%3}, [%4];"
                 : "=r"(r[0]), "=r"(r[1]), "=r"(r[2]), "=r"(r[3]) : "r"(addr));
}

__device__ __forceinline__ void mma_f16(float c[4], const uint32_t a[4], const uint32_t b[2]) {
    asm volatile(
        "mma.sync.aligned.m16n8k16.row.col.f32.f16.f16.f32 "
        "{%0,%1,%2,%3}, {%4,%5,%6,%7}, {%8,%9}, {%0,%1,%2,%3};\n"
        : "+f"(c[0]), "+f"(c[1]), "+f"(c[2]), "+f"(c[3])
        : "r"(a[0]), "r"(a[1]), "r"(a[2]), "r"(a[3]),
          "r"(b[0]), "r"(b[1]));
}

// ============================================================================
// Shared GEMM mainloop+epilogue.
//   A fp16 [M, lda], Bt fp16 [N, ldb] K-major (use k range [0,K)), C [*, ldc].
// ============================================================================
__device__ __forceinline__ void gemm_core(
    const __half* __restrict__ A, int lda, const __half* __restrict__ Bt, int ldb,
    const float* __restrict__ bias, void* __restrict__ Cv, int ldc,
    int K, int relu, int c_half, int tileM, int tileN, uint32_t sbase)
{
    const int tid  = threadIdx.x;
    const int warp = tid >> 5;
    const int lane = tid & 31;
    const int wm = warp & 3;
    const int wn = warp >> 2;

    float acc[2][8][4];
#pragma unroll
    for (int mi = 0; mi < 2; mi++)
#pragma unroll
        for (int ni = 0; ni < 8; ni++)
#pragma unroll
            for (int j = 0; j < 4; j++) acc[mi][ni][j] = 0.0f;

    auto stage = [&](int s, int k0) {
        const uint32_t abase = sbase + s * (STAGE_ALL * 2);
        const uint32_t bbase = abase + STAGE_H * 2;
#pragma unroll
        for (int i = 0; i < 4; i++) {
            int ch  = tid + i * 256;
            int row = ch >> 3;
            int co  = (ch & 7) << 3;
            cp16(abase + (row * LSTR + co) * 2, A  + (size_t)(tileM + row) * lda + k0 + co);
            cp16(bbase + (row * LSTR + co) * 2, Bt + (size_t)(tileN + row) * ldb + k0 + co);
        }
        asm volatile("cp.async.commit_group;\n" ::);
    };

    const int arow = lane & 15;
    const int acol = (lane >> 4) << 3;
    const int bg   = lane >> 3;
    const int brow = ((bg >> 1) << 3) + (lane & 7);
    const int bcol = (bg & 1) << 3;

    const int KT = K / BK;
    stage(0, 0);
    stage(1, BK);

    int cons = 0, ss = 2;
    for (int kt = 0; kt < KT; kt++) {
        if (kt + 1 < KT) asm volatile("cp.async.wait_group 1;\n" ::);
        else             asm volatile("cp.async.wait_group 0;\n" ::);
        __syncthreads();

        const uint32_t abase = sbase + cons * (STAGE_ALL * 2);
        const uint32_t bbase = abase + STAGE_H * 2;

#pragma unroll
        for (int kk = 0; kk < 4; kk++) {
            const int kb = kk << 4;
            uint32_t af[2][4], bf[8][2];
#pragma unroll
            for (int mi = 0; mi < 2; mi++) {
                int m0 = wm * 32 + mi * 16;
                ldsm4(af[mi], abase + ((m0 + arow) * LSTR + kb + acol) * 2);
            }
#pragma unroll
            for (int p = 0; p < 4; p++) {
                int n0 = wn * 64 + p * 16;
                uint32_t r[4];
                ldsm4(r, bbase + ((n0 + brow) * LSTR + kb + bcol) * 2);
                bf[2 * p][0] = r[0]; bf[2 * p][1] = r[1];
                bf[2 * p + 1][0] = r[2]; bf[2 * p + 1][1] = r[3];
            }
#pragma unroll
            for (int mi = 0; mi < 2; mi++)
#pragma unroll
                for (int ni = 0; ni < 8; ni++)
                    mma_f16(acc[mi][ni], af[mi], bf[ni]);
        }

        if (kt + 2 < KT) stage(ss, (kt + 2) * BK);
        if (++cons == NSTAGE) cons = 0;
        if (++ss == NSTAGE) ss = 0;
    }

#pragma unroll
    for (int mi = 0; mi < 2; mi++) {
#pragma unroll
        for (int ni = 0; ni < 8; ni++) {
            int m = tileM + wm * 32 + mi * 16 + (lane >> 2);
            int n = tileN + wn * 64 + ni * 8 + ((lane & 3) << 1);
            float b0 = bias[n], b1 = bias[n + 1];
            float v0 = acc[mi][ni][0] + b0;
            float v1 = acc[mi][ni][1] + b1;
            float v2 = acc[mi][ni][2] + b0;
            float v3 = acc[mi][ni][3] + b1;
            if (relu) {
                v0 = fmaxf(v0, 0.0f); v1 = fmaxf(v1, 0.0f);
                v2 = fmaxf(v2, 0.0f); v3 = fmaxf(v3, 0.0f);
            }
            if (c_half) {
                __half* C = (__half*)Cv;
                *(__half2*)&C[(size_t)m * ldc + n]       = __floats2half2_rn(v0, v1);
                *(__half2*)&C[(size_t)(m + 8) * ldc + n] = __floats2half2_rn(v2, v3);
            } else {
                float* C = (float*)Cv;
                *(float2*)&C[(size_t)m * ldc + n]       = make_float2(v0, v1);
                *(float2*)&C[(size_t)(m + 8) * ldc + n] = make_float2(v2, v3);
            }
        }
    }
}

// ---- general GEMM wrapper ---------------------------------------------------
__global__ __launch_bounds__(256, 2)
void gemm_k(const __half* __restrict__ A, int lda, const __half* __restrict__ Bt,
            const float* __restrict__ bias, void* __restrict__ Cv, int ldc,
            int K, int relu, int c_half)
{
    extern __shared__ __half sm[];
    gemm_core(A, lda, Bt, K, bias, Cv, ldc, K, relu, c_half,
              blockIdx.y * BM, blockIdx.x * BN,
              (uint32_t)__cvta_generic_to_shared(sm));
}

// ---- layer-2 pair, z-batched: serelu[z] = relu(hidden_se[:, z*3072:] @ w2cat[z]) ----
__global__ __launch_bounds__(256, 2)
void gemm_l2(const __half* __restrict__ hidden, const __half* __restrict__ w2cat,
             const float* __restrict__ b2cat, __half* __restrict__ serelu)
{
    extern __shared__ __half sm[];
    const int z = blockIdx.z;
    gemm_core(hidden + z * 3072, 6144,
              w2cat + (size_t)z * 768 * 3072, 3072,
              b2cat + z * 768,
              serelu + (size_t)z * 4096 * 768, 768,
              3072, 1, 1,
              blockIdx.y * BM, blockIdx.x * BN,
              (uint32_t)__cvta_generic_to_shared(sm));
}

// ---- U/V pair, z-batched: uv[z] = serelu[z] @ ow1t[:, z*768:(z+1)*768]  (fp32, no act)
__global__ __launch_bounds__(256, 2)
void gemm_uv(const __half* __restrict__ serelu, const __half* __restrict__ ow1t,
             const float* __restrict__ zbias, float* __restrict__ uv)
{
    extern __shared__ __half sm[];
    const int z = blockIdx.z;
    gemm_core(serelu + (size_t)z * 4096 * 768, 768,
              ow1t + z * 768, 1536,           // K-offset into [3072,1536] K-major
              zbias,
              uv + (size_t)z * 4096 * 3072, 3072,
              768, 0, 0,
              blockIdx.y * BM, blockIdx.x * BN,
              (uint32_t)__cvta_generic_to_shared(sm));
}

// ---- gather + add + bias + relu -> fp16 hidden ------------------------------
//   hidden[r,:] = relu(U[b,i0(r),:] + V[b,i1(r),:] + ob1)    r in [0,49152)
__global__ void gather_add_relu(const float* __restrict__ uv, const int* __restrict__ span,
                                const float* __restrict__ ob1, __half* __restrict__ Hout)
{
    const int r  = blockIdx.x;
    const int b  = r / 6144;
    const int c  = threadIdx.x << 3;    // 384 threads x 8 cols
    const int i0 = span[2 * (size_t)r];
    const int i1 = span[2 * (size_t)r + 1];

    const float* __restrict__ U = uv;
    const float* __restrict__ V = uv + (size_t)4096 * 3072;
    const float* up = U + (size_t)(b * 512 + i0) * 3072 + c;
    const float* vp = V + (size_t)(b * 512 + i1) * 3072 + c;

    float4 u0 = *(const float4*)(up);
    float4 u1 = *(const float4*)(up + 4);
    float4 v0 = *(const float4*)(vp);
    float4 v1 = *(const float4*)(vp + 4);
    float4 b0 = *(const float4*)(ob1 + c);
    float4 b1 = *(const float4*)(ob1 + c + 4);

    float w0 = fmaxf(u0.x + v0.x + b0.x, 0.0f);
    float w1 = fmaxf(u0.y + v0.y + b0.y, 0.0f);
    float w2 = fmaxf(u0.z + v0.z + b0.z, 0.0f);
    float w3 = fmaxf(u0.w + v0.w + b0.w, 0.0f);
    float w4 = fmaxf(u1.x + v1.x + b1.x, 0.0f);
    float w5 = fmaxf(u1.y + v1.y + b1.y, 0.0f);
    float w6 = fmaxf(u1.z + v1.z + b1.z, 0.0f);
    float w7 = fmaxf(u1.w + v1.w + b1.w, 0.0f);

    uint4 o;
    ((__half2*)&o)[0] = __floats2half2_rn(w0, w1);
    ((__half2*)&o)[1] = __floats2half2_rn(w2, w3);
    ((__half2*)&o)[2] = __floats2half2_rn(w4, w5);
    ((__half2*)&o)[3] = __floats2half2_rn(w6, w7);
    *(uint4*)&Hout[(size_t)r * 3072 + c] = o;
}

// ---- fused weight prep: all 6 transposes (+fp16) in ONE launch --------------
__global__ void transpose_all(const float* sw1, const float* ew1, const float* ow1,
                              const float* sw2, const float* ew2, const float* ow2,
                              __half* w1cat, __half* w2cat, __half* ow1t, __half* ow2t)
{
    const float* in; __half* out; int R, C;
    switch (blockIdx.z) {
        case 0: in = sw1; out = w1cat;                          R =  768; C = 3072; break;
        case 1: in = ew1; out = w1cat + (size_t)3072 * 768;     R =  768; C = 3072; break;
        case 2: in = ow1; out = ow1t;                           R = 1536; C = 3072; break;
        case 3: in = sw2; out = w2cat;                          R = 3072; C =  768; break;
        case 4: in = ew2; out = w2cat + (size_t)768 * 3072;     R = 3072; C =  768; break;
        default:in = ow2; out = ow2t;                           R = 3072; C =  768; break;
    }
    const int x0 = blockIdx.x * 32, y0 = blockIdx.y * 32;
    if (x0 >= C || y0 >= R) return;

    __shared__ float t[32][33];
    const int tx = threadIdx.x, ty = threadIdx.y;   // 32 x 8
#pragma unroll
    for (int i = 0; i < 32; i += 8)
        t[ty + i][tx] = in[(size_t)(y0 + ty + i) * C + x0 + tx];
    __syncthreads();
#pragma unroll
    for (int i = 0; i < 32; i += 8)
        out[(size_t)(x0 + ty + i) * R + y0 + tx] = __float2half_rn(t[tx][ty + i]);
}

// ---- bias concats + h convert ----------------------------------------------
__global__ void bias_cat(const float* sb1, const float* eb1, const float* sb2, const float* eb2,
                         float* b1cat, float* b2cat)
{
    int i = blockIdx.x * 256 + threadIdx.x;
    if (i < 3072) { b1cat[i] = sb1[i]; b1cat[3072 + i] = eb1[i]; }
    if (i < 768)  { b2cat[i] = sb2[i]; b2cat[768 + i]  = eb2[i]; }
}

__global__ void f2h_kernel(const float* __restrict__ in, __half* __restrict__ out, int n)
{
    int i = blockIdx.x * 256 + threadIdx.x;
    if (i < n) out[i] = __float2half_rn(in[i]);
}

extern "C" void kernel_launch(void* const* d_in, const int* in_sizes, int n_in,
                              void* d_out, int out_size)
{
    const float* h    = (const float*)d_in[0];
    const int*   span = (const int*)  d_in[1];
    const float* sw1  = (const float*)d_in[2];
    const float* sb1  = (const float*)d_in[3];
    const float* sw2  = (const float*)d_in[4];
    const float* sb2  = (const float*)d_in[5];
    const float* ew1  = (const float*)d_in[6];
    const float* eb1  = (const float*)d_in[7];
    const float* ew2  = (const float*)d_in[8];
    const float* eb2  = (const float*)d_in[9];
    const float* ow1  = (const float*)d_in[10];
    const float* ob1  = (const float*)d_in[11];
    const float* ow2  = (const float*)d_in[12];
    const float* ob2  = (const float*)d_in[13];
    float* out = (float*)d_out;

    __half *hidden, *serelu, *hh, *w1cat, *w2cat, *ow1t, *ow2t;
    float *uv, *b1cat, *b2cat, *zbias;
    cudaGetSymbolAddress((void**)&hidden, g_hidden);
    cudaGetSymbolAddress((void**)&serelu, g_serelu);
    cudaGetSymbolAddress((void**)&hh,     g_hh);
    cudaGetSymbolAddress((void**)&w1cat,  g_w1cat);
    cudaGetSymbolAddress((void**)&w2cat,  g_w2cat);
    cudaGetSymbolAddress((void**)&ow1t,   g_ow1t);
    cudaGetSymbolAddress((void**)&ow2t,   g_ow2t);
    cudaGetSymbolAddress((void**)&uv,     g_uv);
    cudaGetSymbolAddress((void**)&b1cat,  g_b1cat);
    cudaGetSymbolAddress((void**)&b2cat,  g_b2cat);
    cudaGetSymbolAddress((void**)&zbias,  g_zbias);

    cudaFuncSetAttribute(gemm_k,  cudaFuncAttributeMaxDynamicSharedMemorySize, GSMEM_BYTES);
    cudaFuncSetAttribute(gemm_l2, cudaFuncAttributeMaxDynamicSharedMemorySize, GSMEM_BYTES);
    cudaFuncSetAttribute(gemm_uv, cudaFuncAttributeMaxDynamicSharedMemorySize, GSMEM_BYTES);

    // 1: weight transposes   2: bias concats   3: h -> fp16
    transpose_all<<<dim3(96, 96, 6), dim3(32, 8)>>>(sw1, ew1, ow1, sw2, ew2, ow2,
                                                    w1cat, w2cat, ow1t, ow2t);
    bias_cat<<<12, 256>>>(sb1, eb1, sb2, eb2, b1cat, b2cat);
    f2h_kernel<<<(3145728 + 255) / 256, 256>>>(h, hh, 3145728);

    const dim3 blk(256);
    // 4: fused layer-1  hidden_se[4096,6144] = relu(hh @ w1cat + b1cat)
    gemm_k<<<dim3(48, 32), blk, GSMEM_BYTES>>>(hh, 768, w1cat, b1cat, hidden, 6144,
                                               768, 1, 1);
    // 5: batched layer-2  serelu[z] = relu(hidden_se[:, z] @ w2cat[z] + b2cat[z])
    gemm_l2<<<dim3(6, 32, 2), blk, GSMEM_BYTES>>>(hidden, w2cat, b2cat, serelu);
    // 6: U/V projections  uv[z] = serelu[z] @ ow1_half[z]   (fp32)
    gemm_uv<<<dim3(24, 32, 2), blk, GSMEM_BYTES>>>(serelu, ow1t, zbias, uv);
    // 7: gather + add + relu  hidden[49152,3072] (fp16)
    gather_add_relu<<<49152, 384>>>(uv, span, ob1, hidden);
    // 8: final  out[49152,768] = hidden @ ow2t + ob2
    gemm_k<<<dim3(6, 384), blk, GSMEM_BYTES>>>(hidden, 3072, ow2t, ob2, out, 768,
                                               3072, 0, 0);
}

// round 11
// speedup vs baseline: 2.3648x; 1.0295x over previous
#include <cuda_runtime.h>
#include <cuda_fp16.h>
#include <cstdint>
#include <cstddef>

// ============================================================================
// SpanMarkerV1 on sm_100: fp16 mma.sync m16n8k16, fp32 accum.
//   B=8, L=512, D=768, S=6144, H=3072
// Pipeline: L1 fused pair GEMM -> L2 z-batched GEMM -> U/V projections (fp16)
//   -> gather+add+relu bandwidth pass -> final GEMM.
// (cat @ ow1 splits into U = serelu_s @ ow1_top, V = serelu_e @ ow1_bot since
// gathered rows repeat ~12x; this round U/V stored fp16 to halve gather traffic.)
// GEMM core: 128x128x64 tiles, 32x64 warp tiles, 3-stage cp.async ring,
// ldmatrix.x4, stride-72-half smem, 2 CTAs/SM.
// ============================================================================

#define BM 128
#define BN 128
#define BK 64
#define LSTR 72                         // halves; 144B row stride, conflict-free
#define STAGE_H (BM * LSTR)             // 9216 halves per operand tile
#define STAGE_ALL (2 * STAGE_H)         // A + B per stage (halves)
#define NSTAGE 3
#define GSMEM_BYTES (NSTAGE * STAGE_ALL * 2)  // 110592 bytes

// -------- scratch (device globals; allocations are forbidden) ---------------
__device__ __half g_hidden[150994944ULL]; // reused: [4096,6144] then [49152,3072]
__device__ __half g_serelu[6291456ULL];   // [2][4096,768] relu'd reps
__device__ __half g_hh[3145728ULL];       // h in fp16
__device__ __half g_w1cat[4718592ULL];    // [6144,768]  = [sw1t; ew1t]
__device__ __half g_w2cat[4718592ULL];    // [1536,3072] = [sw2t; ew2t]
__device__ __half g_ow1t[4718592ULL];     // [3072,1536]
__device__ __half g_ow2t[2359296ULL];     // [768,3072]
__device__ __half g_uv[25165824ULL];      // [2][4096,3072] fp16 U,V (48 MB)
__device__ float  g_b1cat[6144];
__device__ float  g_b2cat[1536];
__device__ float  g_zbias[3072];          // zero-initialized

__device__ __forceinline__ void cp16(uint32_t smem_addr, const void* gmem_ptr) {
    asm volatile("cp.async.cg.shared.global [%0], [%1], 16;\n" :: "r"(smem_addr), "l"(gmem_ptr));
}

__device__ __forceinline__ void ldsm4(uint32_t* r, uint32_t addr) {
    asm volatile("ldmatrix.sync.aligned.m8n8.x4.shared.b16 {%0,%1,%2,%3}, [%4];"
                 : "=r"(r[0]), "=r"(r[1]), "=r"(r[2]), "=r"(r[3]) : "r"(addr));
}

__device__ __forceinline__ void mma_f16(float c[4], const uint32_t a[4], const uint32_t b[2]) {
    asm volatile(
        "mma.sync.aligned.m16n8k16.row.col.f32.f16.f16.f32 "
        "{%0,%1,%2,%3}, {%4,%5,%6,%7}, {%8,%9}, {%0,%1,%2,%3};\n"
        : "+f"(c[0]), "+f"(c[1]), "+f"(c[2]), "+f"(c[3])
        : "r"(a[0]), "r"(a[1]), "r"(a[2]), "r"(a[3]),
          "r"(b[0]), "r"(b[1]));
}

// ============================================================================
// Shared GEMM mainloop+epilogue.
//   A fp16 [M, lda], Bt fp16 [N, ldb] K-major (k range [0,K)), C [*, ldc].
// ============================================================================
__device__ __forceinline__ void gemm_core(
    const __half* __restrict__ A, int lda, const __half* __restrict__ Bt, int ldb,
    const float* __restrict__ bias, void* __restrict__ Cv, int ldc,
    int K, int relu, int c_half, int tileM, int tileN, uint32_t sbase)
{
    const int tid  = threadIdx.x;
    const int warp = tid >> 5;
    const int lane = tid & 31;
    const int wm = warp & 3;
    const int wn = warp >> 2;

    float acc[2][8][4];
#pragma unroll
    for (int mi = 0; mi < 2; mi++)
#pragma unroll
        for (int ni = 0; ni < 8; ni++)
#pragma unroll
            for (int j = 0; j < 4; j++) acc[mi][ni][j] = 0.0f;

    auto stage = [&](int s, int k0) {
        const uint32_t abase = sbase + s * (STAGE_ALL * 2);
        const uint32_t bbase = abase + STAGE_H * 2;
#pragma unroll
        for (int i = 0; i < 4; i++) {
            int ch  = tid + i * 256;
            int row = ch >> 3;
            int co  = (ch & 7) << 3;
            cp16(abase + (row * LSTR + co) * 2, A  + (size_t)(tileM + row) * lda + k0 + co);
            cp16(bbase + (row * LSTR + co) * 2, Bt + (size_t)(tileN + row) * ldb + k0 + co);
        }
        asm volatile("cp.async.commit_group;\n" ::);
    };

    const int arow = lane & 15;
    const int acol = (lane >> 4) << 3;
    const int bg   = lane >> 3;
    const int brow = ((bg >> 1) << 3) + (lane & 7);
    const int bcol = (bg & 1) << 3;

    const int KT = K / BK;
    stage(0, 0);
    stage(1, BK);

    int cons = 0, ss = 2;
    for (int kt = 0; kt < KT; kt++) {
        if (kt + 1 < KT) asm volatile("cp.async.wait_group 1;\n" ::);
        else             asm volatile("cp.async.wait_group 0;\n" ::);
        __syncthreads();

        const uint32_t abase = sbase + cons * (STAGE_ALL * 2);
        const uint32_t bbase = abase + STAGE_H * 2;

#pragma unroll
        for (int kk = 0; kk < 4; kk++) {
            const int kb = kk << 4;
            uint32_t af[2][4], bf[8][2];
#pragma unroll
            for (int mi = 0; mi < 2; mi++) {
                int m0 = wm * 32 + mi * 16;
                ldsm4(af[mi], abase + ((m0 + arow) * LSTR + kb + acol) * 2);
            }
#pragma unroll
            for (int p = 0; p < 4; p++) {
                int n0 = wn * 64 + p * 16;
                uint32_t r[4];
                ldsm4(r, bbase + ((n0 + brow) * LSTR + kb + bcol) * 2);
                bf[2 * p][0] = r[0]; bf[2 * p][1] = r[1];
                bf[2 * p + 1][0] = r[2]; bf[2 * p + 1][1] = r[3];
            }
#pragma unroll
            for (int mi = 0; mi < 2; mi++)
#pragma unroll
                for (int ni = 0; ni < 8; ni++)
                    mma_f16(acc[mi][ni], af[mi], bf[ni]);
        }

        if (kt + 2 < KT) stage(ss, (kt + 2) * BK);
        if (++cons == NSTAGE) cons = 0;
        if (++ss == NSTAGE) ss = 0;
    }

#pragma unroll
    for (int mi = 0; mi < 2; mi++) {
#pragma unroll
        for (int ni = 0; ni < 8; ni++) {
            int m = tileM + wm * 32 + mi * 16 + (lane >> 2);
            int n = tileN + wn * 64 + ni * 8 + ((lane & 3) << 1);
            float b0 = bias[n], b1 = bias[n + 1];
            float v0 = acc[mi][ni][0] + b0;
            float v1 = acc[mi][ni][1] + b1;
            float v2 = acc[mi][ni][2] + b0;
            float v3 = acc[mi][ni][3] + b1;
            if (relu) {
                v0 = fmaxf(v0, 0.0f); v1 = fmaxf(v1, 0.0f);
                v2 = fmaxf(v2, 0.0f); v3 = fmaxf(v3, 0.0f);
            }
            if (c_half) {
                __half* C = (__half*)Cv;
                *(__half2*)&C[(size_t)m * ldc + n]       = __floats2half2_rn(v0, v1);
                *(__half2*)&C[(size_t)(m + 8) * ldc + n] = __floats2half2_rn(v2, v3);
            } else {
                float* C = (float*)Cv;
                *(float2*)&C[(size_t)m * ldc + n]       = make_float2(v0, v1);
                *(float2*)&C[(size_t)(m + 8) * ldc + n] = make_float2(v2, v3);
            }
        }
    }
}

// ---- general GEMM wrapper ---------------------------------------------------
__global__ __launch_bounds__(256, 2)
void gemm_k(const __half* __restrict__ A, int lda, const __half* __restrict__ Bt,
            const float* __restrict__ bias, void* __restrict__ Cv, int ldc,
            int K, int relu, int c_half)
{
    extern __shared__ __half sm[];
    gemm_core(A, lda, Bt, K, bias, Cv, ldc, K, relu, c_half,
              blockIdx.y * BM, blockIdx.x * BN,
              (uint32_t)__cvta_generic_to_shared(sm));
}

// ---- layer-2 pair, z-batched: serelu[z] = relu(hidden_se[:, z*3072:] @ w2cat[z]) ----
__global__ __launch_bounds__(256, 2)
void gemm_l2(const __half* __restrict__ hidden, const __half* __restrict__ w2cat,
             const float* __restrict__ b2cat, __half* __restrict__ serelu)
{
    extern __shared__ __half sm[];
    const int z = blockIdx.z;
    gemm_core(hidden + z * 3072, 6144,
              w2cat + (size_t)z * 768 * 3072, 3072,
              b2cat + z * 768,
              serelu + (size_t)z * 4096 * 768, 768,
              3072, 1, 1,
              blockIdx.y * BM, blockIdx.x * BN,
              (uint32_t)__cvta_generic_to_shared(sm));
}

// ---- U/V pair, z-batched (fp16 out): uv[z] = serelu[z] @ ow1t[:, z*768:(z+1)*768] ----
__global__ __launch_bounds__(256, 2)
void gemm_uv(const __half* __restrict__ serelu, const __half* __restrict__ ow1t,
             const float* __restrict__ zbias, __half* __restrict__ uv)
{
    extern __shared__ __half sm[];
    const int z = blockIdx.z;
    gemm_core(serelu + (size_t)z * 4096 * 768, 768,
              ow1t + z * 768, 1536,           // K-offset into [3072,1536] K-major
              zbias,
              uv + (size_t)z * 4096 * 3072, 3072,
              768, 0, 1,
              blockIdx.y * BM, blockIdx.x * BN,
              (uint32_t)__cvta_generic_to_shared(sm));
}

// ---- gather + add + bias + relu -> fp16 hidden ------------------------------
//   hidden[r,:] = relu(U[b,i0(r),:] + V[b,i1(r),:] + ob1)    r in [0,49152)
__global__ void gather_add_relu(const __half* __restrict__ uv, const int* __restrict__ span,
                                const float* __restrict__ ob1, __half* __restrict__ Hout)
{
    const int r  = blockIdx.x;
    const int b  = r / 6144;
    const int c  = threadIdx.x << 3;    // 384 threads x 8 cols
    const int i0 = span[2 * (size_t)r];
    const int i1 = span[2 * (size_t)r + 1];

    const __half* __restrict__ U = uv;
    const __half* __restrict__ V = uv + (size_t)4096 * 3072;
    uint4 uu = *(const uint4*)(U + (size_t)(b * 512 + i0) * 3072 + c);
    uint4 vv = *(const uint4*)(V + (size_t)(b * 512 + i1) * 3072 + c);
    float4 b0 = *(const float4*)(ob1 + c);
    float4 b1 = *(const float4*)(ob1 + c + 4);
    const float* bb = (const float*)&b0;   // b0/b1 contiguous on stack? avoid: use arrays

    float bias8[8];
    *(float4*)&bias8[0] = b0;
    *(float4*)&bias8[4] = b1;

    const __half2* up = (const __half2*)&uu;
    const __half2* vp = (const __half2*)&vv;
    uint4 o;
    __half2* op = (__half2*)&o;
#pragma unroll
    for (int j = 0; j < 4; j++) {
        float2 uf = __half22float2(up[j]);
        float2 vf = __half22float2(vp[j]);
        float w0 = fmaxf(uf.x + vf.x + bias8[2 * j],     0.0f);
        float w1 = fmaxf(uf.y + vf.y + bias8[2 * j + 1], 0.0f);
        op[j] = __floats2half2_rn(w0, w1);
    }
    *(uint4*)&Hout[(size_t)r * 3072 + c] = o;
    (void)bb;
}

// ---- fused weight prep: all 6 transposes (+fp16) in ONE launch --------------
__global__ void transpose_all(const float* sw1, const float* ew1, const float* ow1,
                              const float* sw2, const float* ew2, const float* ow2,
                              __half* w1cat, __half* w2cat, __half* ow1t, __half* ow2t)
{
    const float* in; __half* out; int R, C;
    switch (blockIdx.z) {
        case 0: in = sw1; out = w1cat;                          R =  768; C = 3072; break;
        case 1: in = ew1; out = w1cat + (size_t)3072 * 768;     R =  768; C = 3072; break;
        case 2: in = ow1; out = ow1t;                           R = 1536; C = 3072; break;
        case 3: in = sw2; out = w2cat;                          R = 3072; C =  768; break;
        case 4: in = ew2; out = w2cat + (size_t)768 * 3072;     R = 3072; C =  768; break;
        default:in = ow2; out = ow2t;                           R = 3072; C =  768; break;
    }
    const int x0 = blockIdx.x * 32, y0 = blockIdx.y * 32;
    if (x0 >= C || y0 >= R) return;

    __shared__ float t[32][33];
    const int tx = threadIdx.x, ty = threadIdx.y;   // 32 x 8
#pragma unroll
    for (int i = 0; i < 32; i += 8)
        t[ty + i][tx] = in[(size_t)(y0 + ty + i) * C + x0 + tx];
    __syncthreads();
#pragma unroll
    for (int i = 0; i < 32; i += 8)
        out[(size_t)(x0 + ty + i) * R + y0 + tx] = __float2half_rn(t[tx][ty + i]);
}

// ---- bias concats + h convert ----------------------------------------------
__global__ void bias_cat(const float* sb1, const float* eb1, const float* sb2, const float* eb2,
                         float* b1cat, float* b2cat)
{
    int i = blockIdx.x * 256 + threadIdx.x;
    if (i < 3072) { b1cat[i] = sb1[i]; b1cat[3072 + i] = eb1[i]; }
    if (i < 768)  { b2cat[i] = sb2[i]; b2cat[768 + i]  = eb2[i]; }
}

__global__ void f2h_kernel(const float* __restrict__ in, __half* __restrict__ out, int n)
{
    int i = blockIdx.x * 256 + threadIdx.x;
    if (i < n) out[i] = __float2half_rn(in[i]);
}

extern "C" void kernel_launch(void* const* d_in, const int* in_sizes, int n_in,
                              void* d_out, int out_size)
{
    const float* h    = (const float*)d_in[0];
    const int*   span = (const int*)  d_in[1];
    const float* sw1  = (const float*)d_in[2];
    const float* sb1  = (const float*)d_in[3];
    const float* sw2  = (const float*)d_in[4];
    const float* sb2  = (const float*)d_in[5];
    const float* ew1  = (const float*)d_in[6];
    const float* eb1  = (const float*)d_in[7];
    const float* ew2  = (const float*)d_in[8];
    const float* eb2  = (const float*)d_in[9];
    const float* ow1  = (const float*)d_in[10];
    const float* ob1  = (const float*)d_in[11];
    const float* ow2  = (const float*)d_in[12];
    const float* ob2  = (const float*)d_in[13];
    float* out = (float*)d_out;

    __half *hidden, *serelu, *hh, *w1cat, *w2cat, *ow1t, *ow2t, *uv;
    float *b1cat, *b2cat, *zbias;
    cudaGetSymbolAddress((void**)&hidden, g_hidden);
    cudaGetSymbolAddress((void**)&serelu, g_serelu);
    cudaGetSymbolAddress((void**)&hh,     g_hh);
    cudaGetSymbolAddress((void**)&w1cat,  g_w1cat);
    cudaGetSymbolAddress((void**)&w2cat,  g_w2cat);
    cudaGetSymbolAddress((void**)&ow1t,   g_ow1t);
    cudaGetSymbolAddress((void**)&ow2t,   g_ow2t);
    cudaGetSymbolAddress((void**)&uv,     g_uv);
    cudaGetSymbolAddress((void**)&b1cat,  g_b1cat);
    cudaGetSymbolAddress((void**)&b2cat,  g_b2cat);
    cudaGetSymbolAddress((void**)&zbias,  g_zbias);

    cudaFuncSetAttribute(gemm_k,  cudaFuncAttributeMaxDynamicSharedMemorySize, GSMEM_BYTES);
    cudaFuncSetAttribute(gemm_l2, cudaFuncAttributeMaxDynamicSharedMemorySize, GSMEM_BYTES);
    cudaFuncSetAttribute(gemm_uv, cudaFuncAttributeMaxDynamicSharedMemorySize, GSMEM_BYTES);

    // 1: weight transposes   2: bias concats   3: h -> fp16
    transpose_all<<<dim3(96, 96, 6), dim3(32, 8)>>>(sw1, ew1, ow1, sw2, ew2, ow2,
                                                    w1cat, w2cat, ow1t, ow2t);
    bias_cat<<<12, 256>>>(sb1, eb1, sb2, eb2, b1cat, b2cat);
    f2h_kernel<<<(3145728 + 255) / 256, 256>>>(h, hh, 3145728);

    const dim3 blk(256);
    // 4: fused layer-1  hidden_se[4096,6144] = relu(hh @ w1cat + b1cat)
    gemm_k<<<dim3(48, 32), blk, GSMEM_BYTES>>>(hh, 768, w1cat, b1cat, hidden, 6144,
                                               768, 1, 1);
    // 5: batched layer-2  serelu[z] = relu(hidden_se[:, z] @ w2cat[z] + b2cat[z])
    gemm_l2<<<dim3(6, 32, 2), blk, GSMEM_BYTES>>>(hidden, w2cat, b2cat, serelu);
    // 6: U/V projections (fp16)  uv[z] = serelu[z] @ ow1_half[z]
    gemm_uv<<<dim3(24, 32, 2), blk, GSMEM_BYTES>>>(serelu, ow1t, zbias, uv);
    // 7: gather + add + relu  hidden[49152,3072] (fp16)
    gather_add_relu<<<49152, 384>>>(uv, span, ob1, hidden);
    // 8: final  out[49152,768] = hidden @ ow2t + ob2
    gemm_k<<<dim3(6, 384), blk, GSMEM_BYTES>>>(hidden, 3072, ow2t, ob2, out, 768,
                                               3072, 0, 0);
}